// round 16
// baseline (speedup 1.0000x reference)
#include <cuda_runtime.h>
#include <cuda_fp16.h>
#include <math.h>
#include <stdint.h>

#define T_TOK 4096
#define D_MODEL 512
#define E_EXP 8
#define H_HID 1024
#define DFF_DIM 2048

// ---------------- scratch ------------------------------------------------------
__device__ __align__(16) __half g_xs16[T_TOK * D_MODEL];
__device__ __align__(16) __half g_xln16[T_TOK * D_MODEL];
__device__ __align__(16) __half g_xin16[T_TOK * D_MODEL];
__device__ __align__(16) __half g_feat16[T_TOK * 64];
__device__ __align__(16) __half g_t116[(size_t)T_TOK * DFF_DIM];
__device__ __align__(16) __half g_h116[(size_t)E_EXP * T_TOK * H_HID];
__device__ __align__(16) __half g_fc1h[(size_t)DFF_DIM * D_MODEL], g_fc1l[(size_t)DFF_DIM * D_MODEL];
__device__ __align__(16) __half g_fc2h[(size_t)D_MODEL * DFF_DIM], g_fc2l[(size_t)D_MODEL * DFF_DIM];
__device__ __align__(16) __half g_w1h[(size_t)E_EXP * H_HID * D_MODEL], g_w1l[(size_t)E_EXP * H_HID * D_MODEL];
__device__ __align__(16) __half g_w2h[(size_t)E_EXP * D_MODEL * H_HID], g_w2l[(size_t)E_EXP * D_MODEL * H_HID];
__device__ __align__(16) __half g_fwh[1024 * 64], g_fwl[1024 * 64];   // film_w^T, interleaved
__device__ __align__(16) float g_sh[T_TOK * D_MODEL];
__device__ __align__(16) float g_sh2[T_TOK * D_MODEL];
__device__ __align__(16) float g_moe2[T_TOK * 2 * D_MODEL];
__device__ __align__(16) float g_moe2b[T_TOK * 2 * D_MODEL];
__device__ int   g_cnt[E_EXP];
__device__ int   g_list[E_EXP * T_TOK];
__device__ float g_glist[E_EXP * T_TOK];

__device__ __forceinline__ float gelu_tanh(float x) {
    float x3 = x * x * x;
    return 0.5f * x * (1.0f + tanhf(0.7978845608028654f * (x + 0.044715f * x3)));
}

__device__ __forceinline__ uint32_t smem_u32(const void* p) {
    uint32_t a;
    asm("{ .reg .u64 t; cvta.to.shared.u64 t, %1; cvt.u32.u64 %0, t; }" : "=r"(a) : "l"(p));
    return a;
}

// ---------------- mma.sync / cp.async helpers ----------------------------------
__device__ __forceinline__ void ldmx4(uint32_t* r, uint32_t a) {
    asm volatile("ldmatrix.sync.aligned.m8n8.x4.shared.b16 {%0,%1,%2,%3}, [%4];"
                 : "=r"(r[0]), "=r"(r[1]), "=r"(r[2]), "=r"(r[3]) : "r"(a));
}
__device__ __forceinline__ void mma_f16(float* c, const uint32_t* a, const uint32_t* b) {
    asm volatile("mma.sync.aligned.m16n8k16.row.col.f32.f16.f16.f32 "
                 "{%0,%1,%2,%3}, {%4,%5,%6,%7}, {%8,%9}, {%0,%1,%2,%3};"
                 : "+f"(c[0]), "+f"(c[1]), "+f"(c[2]), "+f"(c[3])
                 : "r"(a[0]), "r"(a[1]), "r"(a[2]), "r"(a[3]), "r"(b[0]), "r"(b[1]));
}
__device__ __forceinline__ void cpa16(uint32_t dst, const void* src) {
    asm volatile("cp.async.cg.shared.global [%0], [%1], 16;" :: "r"(dst), "l"(src));
}
#define CP_COMMIT() asm volatile("cp.async.commit_group;" ::: "memory")
#define CP_WAIT1()  asm volatile("cp.async.wait_group 1;" ::: "memory")
#define CP_WAIT0()  asm volatile("cp.async.wait_group 0;" ::: "memory")

// ---------------- fused weight transposes (single launch) ----------------------
__device__ __forceinline__ void transpose_body(
    const float* __restrict__ in, __half* __restrict__ oh, __half* __restrict__ ol,
    int Kd, int Nd, int bx, int by, int bz, float* spool, bool il)
{
    in += (size_t)bz * Kd * Nd;
    oh += (size_t)bz * Kd * Nd;
    ol += (size_t)bz * Kd * Nd;
    int n0 = bx * 64, k0 = by * 64;
    int tid = threadIdx.x;
    int kr = tid >> 4, n4 = (tid & 15) * 4;
    #pragma unroll
    for (int it = 0; it < 4; it++) {
        int k = kr + it * 16;
        float4 v = *(const float4*)&in[(size_t)(k0 + k) * Nd + n0 + n4];
        spool[k * 65 + n4 + 0] = v.x; spool[k * 65 + n4 + 1] = v.y;
        spool[k * 65 + n4 + 2] = v.z; spool[k * 65 + n4 + 3] = v.w;
    }
    __syncthreads();
    int n = tid >> 2, kc = (tid & 3) * 16;
    __half hbuf[16], lbuf[16];
    #pragma unroll
    for (int i = 0; i < 16; i++) {
        float v = spool[(kc + i) * 65 + n];
        __half h = __float2half_rn(v);
        hbuf[i] = h;
        lbuf[i] = __float2half_rn(v - __half2float(h));
    }
    int gn = n0 + n;
    int orow = il ? ((gn < 512) ? 2 * gn : 2 * (gn - 512) + 1) : gn;
    size_t base = (size_t)orow * Kd + k0 + kc;
    *(uint4*)&oh[base]     = *(uint4*)&hbuf[0];
    *(uint4*)&oh[base + 8] = *(uint4*)&hbuf[8];
    *(uint4*)&ol[base]     = *(uint4*)&lbuf[0];
    *(uint4*)&ol[base + 8] = *(uint4*)&lbuf[8];
}

// blocks: fc1 256 | fc2 256 | w1 1024 | w2 1024 | filmw 16  = 2576
__global__ void __launch_bounds__(256)
transpose_all(const float* __restrict__ fc1, __half* fc1h, __half* fc1l,
              const float* __restrict__ fc2, __half* fc2h, __half* fc2l,
              const float* __restrict__ w1,  __half* w1h,  __half* w1l,
              const float* __restrict__ w2,  __half* w2h,  __half* w2l,
              const float* __restrict__ fw,  __half* fwh,  __half* fwl)
{
    __shared__ __align__(16) float spool[64 * 65];
    if (blockIdx.x == 0 && threadIdx.x < E_EXP) g_cnt[threadIdx.x] = 0;
    int idx = blockIdx.x;
    if (idx < 256) {
        transpose_body(fc1, fc1h, fc1l, D_MODEL, DFF_DIM, idx & 31, idx >> 5, 0, spool, false);
        return;
    }
    idx -= 256;
    if (idx < 256) {
        transpose_body(fc2, fc2h, fc2l, DFF_DIM, D_MODEL, idx & 7, idx >> 3, 0, spool, false);
        return;
    }
    idx -= 256;
    if (idx < 1024) {
        transpose_body(w1, w1h, w1l, D_MODEL, H_HID, idx & 15, (idx >> 4) & 7, idx >> 7, spool, false);
        return;
    }
    idx -= 1024;
    if (idx < 1024) {
        transpose_body(w2, w2h, w2l, H_HID, D_MODEL, idx & 7, (idx >> 3) & 15, idx >> 7, spool, false);
        return;
    }
    idx -= 1024;  // film_w [64,1024] -> [1024,64] interleaved
    transpose_body(fw, fwh, fwl, 64, 1024, idx, 0, 0, spool, true);
}

// ---------------- per-token prep: LN x2, feat, router ---------------------------
__global__ void prep_kernel(
    const float* __restrict__ hid, const float* __restrict__ raw,
    const float* __restrict__ ln_g, const float* __restrict__ ln_b,
    const float* __restrict__ pg,   const float* __restrict__ pb,
    const float* __restrict__ feat_w, const float* __restrict__ feat_b,
    const float* __restrict__ rw, const float* __restrict__ rb)
{
    int t = blockIdx.x;
    int tid = threadIdx.x;
    int wid = tid >> 5, lane = tid & 31;

    __shared__ float red[8];
    __shared__ float red2[8];
    __shared__ float s_x[D_MODEL];
    __shared__ float s_logits[E_EXP];

    float h0 = hid[t * D_MODEL + tid];
    float h1 = hid[t * D_MODEL + 256 + tid];

    float p = h0 + h1;
    #pragma unroll
    for (int off = 16; off; off >>= 1) p += __shfl_down_sync(0xffffffff, p, off);
    if (lane == 0) red[wid] = p;
    __syncthreads();
    float mean = (red[0] + red[1] + red[2] + red[3] +
                  red[4] + red[5] + red[6] + red[7]) * (1.0f / 512.0f);

    float d0 = h0 - mean, d1 = h1 - mean;
    float q = d0 * d0 + d1 * d1;
    #pragma unroll
    for (int off = 16; off; off >>= 1) q += __shfl_down_sync(0xffffffff, q, off);
    if (lane == 0) red2[wid] = q;
    __syncthreads();
    float inv = rsqrtf((red2[0] + red2[1] + red2[2] + red2[3] +
                        red2[4] + red2[5] + red2[6] + red2[7]) * (1.0f / 512.0f) + 1e-5f);

    float x0 = d0 * inv, x1 = d1 * inv;
    float xl0 = x0 * ln_g[tid]       + ln_b[tid];
    float xl1 = x1 * ln_g[tid + 256] + ln_b[tid + 256];
    s_x[tid]       = xl0;
    s_x[tid + 256] = xl1;
    g_xln16[(size_t)t * D_MODEL + tid]       = __float2half_rn(xl0);
    g_xln16[(size_t)t * D_MODEL + tid + 256] = __float2half_rn(xl1);
    g_xs16[(size_t)t * D_MODEL + tid]       = __float2half_rn(x0 * pg[tid]       + pb[tid]);
    g_xs16[(size_t)t * D_MODEL + tid + 256] = __float2half_rn(x1 * pg[tid + 256] + pb[tid + 256]);

    if (tid < 64) {
        float acc = feat_b[tid];
        #pragma unroll
        for (int i = 0; i < 16; i++) acc += raw[t * 16 + i] * feat_w[i * 64 + tid];
        g_feat16[t * 64 + tid] = __float2half_rn(acc);
    }
    __syncthreads();

    {
        int w = tid >> 5;
        float acc = 0.0f;
        #pragma unroll
        for (int d = 0; d < 512; d += 32) acc += s_x[d + lane] * rw[(d + lane) * E_EXP + w];
        #pragma unroll
        for (int off = 16; off; off >>= 1) acc += __shfl_down_sync(0xffffffff, acc, off);
        if (lane == 0) s_logits[w] = acc + rb[w];
    }
    __syncthreads();

    if (tid == 0) {
        int i0 = 0; float v0 = s_logits[0];
        #pragma unroll
        for (int e = 1; e < E_EXP; e++) { float v = s_logits[e]; if (v > v0) { v0 = v; i0 = e; } }
        int i1 = -1; float v1 = -1e30f;
        #pragma unroll
        for (int e = 0; e < E_EXP; e++) {
            if (e == i0) continue;
            float v = s_logits[e]; if (v > v1) { v1 = v; i1 = e; }
        }
        float b  = expf(v1 - v0);
        float g0 = 1.0f / (1.0f + b);
        float g1 = b * g0;
        int p0 = atomicAdd(&g_cnt[i0], 1);
        g_list[i0 * T_TOK + p0] = t * 2 + 0;  g_glist[i0 * T_TOK + p0] = g0;
        int p1 = atomicAdd(&g_cnt[i1], 1);
        g_list[i1 * T_TOK + p1] = t * 2 + 1;  g_glist[i1 * T_TOK + p1] = g1;
    }
}

// ---------------- GEMM: CTA 128x128, 8 warps 64x32, fp16 2-term ----------------
// K-chunk 64 (144B pitch), 2 stages, 2 CTA/SM. Hoisted cp.async addressing.
#define PITCH 144
#define A_SZ 18432
#define STAGE_SZ 55296
#define GSMEM_SZ (1024 + 2 * STAGE_SZ)   // 111616 -> 2 CTAs/SM

template<int MODE, int N, int KT, int KL>
__device__ __forceinline__ void gemm_body(int bx, int by, int e, int koff, int split,
                                          const float* __restrict__ bi0, char* sm)
{
    constexpr int NC = KL / 64;
    int M = T_TOK;
    if (MODE == 2 || MODE == 3) M = g_cnt[e];
    const int m0 = by * 128;
    if (m0 >= M) return;
    const int n0 = bx * 128;

    const __half *A16, *Bh, *Bl;
    if (MODE == 0) { A16 = g_xs16;  Bh = g_fc1h; Bl = g_fc1l; }
    if (MODE == 1) { A16 = g_t116;  Bh = g_fc2h; Bl = g_fc2l; }
    if (MODE == 2) { A16 = g_xin16;
                     Bh = g_w1h + (size_t)e * N * KT; Bl = g_w1l + (size_t)e * N * KT; }
    if (MODE == 3) { A16 = g_h116 + (size_t)e * T_TOK * KT;
                     Bh = g_w2h + (size_t)e * N * KT; Bl = g_w2l + (size_t)e * N * KT; }
    if (MODE == 4) { A16 = g_feat16; Bh = g_fwh; Bl = g_fwl; }
    const float* bi = bi0 + ((MODE == 2 || MODE == 3) ? e * N : 0);

    int* s_tok = (int*)sm;
    const int tid = threadIdx.x;
    const int wid = tid >> 5, lane = tid & 31;
    const int wm = wid & 1, wn = wid >> 1;

    if (MODE == 2 && tid < 128) {
        int r = m0 + tid;
        s_tok[tid] = (r < M) ? (g_list[e * T_TOK + r] >> 1) : 0;
    }
    __syncthreads();

    const uint32_t smb = smem_u32(sm);

    // hoisted cp.async addressing: tid<256 => mat=u>>2, c16=tid&7, row=(tid>>3)+32*(u&3)
    const int row0 = tid >> 3;
    const int cel  = (tid & 7) * 8;           // halves
    const __half* pA[4];
    #pragma unroll
    for (int u = 0; u < 4; u++) {
        int r = (MODE == 2) ? s_tok[row0 + 32 * u] : (m0 + row0 + 32 * u);
        pA[u] = A16 + (size_t)r * KT + koff + cel;
    }
    const __half* pBh = Bh + (size_t)(n0 + row0) * KT + koff + cel;
    const __half* pBl = Bl + (size_t)(n0 + row0) * KT + koff + cel;
    const uint32_t dbase = row0 * PITCH + (tid & 7) * 16;

    float acc[4][4][4];
    #pragma unroll
    for (int i = 0; i < 4; i++)
        #pragma unroll
        for (int j = 0; j < 4; j++)
            #pragma unroll
            for (int q = 0; q < 4; q++) acc[i][j][q] = 0.0f;

    auto issue = [&](int c) {
        uint32_t st = smb + 1024 + (c & 1) * STAGE_SZ + dbase;
        const int kb = c * 64;
        #pragma unroll
        for (int u = 0; u < 4; u++)
            cpa16(st + u * (32 * PITCH), pA[u] + kb);
        #pragma unroll
        for (int u = 0; u < 4; u++)
            cpa16(st + A_SZ + u * (32 * PITCH), pBh + (size_t)u * 32 * KT + kb);
        #pragma unroll
        for (int u = 0; u < 4; u++)
            cpa16(st + 2 * A_SZ + u * (32 * PITCH), pBl + (size_t)u * 32 * KT + kb);
        CP_COMMIT();
    };

    auto compute = [&](int s) {
        const uint32_t base = smb + 1024 + s * STAGE_SZ;
        #pragma unroll
        for (int ks = 0; ks < 4; ks++) {
            uint32_t ah[4][4];
            uint32_t a_ad = base + ((uint32_t)(wm * 64 + (lane & 15)) * PITCH
                                    + (uint32_t)(ks * 16 + (lane >> 4) * 8) * 2u);
            #pragma unroll
            for (int i = 0; i < 4; i++) ldmx4(ah[i], a_ad + i * (16 * PITCH));
            uint32_t b_ad = base + A_SZ
                + ((uint32_t)(wn * 32 + (lane >> 4) * 8 + (lane & 7)) * PITCH
                   + (uint32_t)(ks * 16 + ((lane >> 3) & 1) * 8) * 2u);
            #pragma unroll
            for (int jj = 0; jj < 2; jj++) {
                uint32_t bh2[4], bl2[4];
                ldmx4(bh2, b_ad + jj * (16 * PITCH));
                ldmx4(bl2, b_ad + A_SZ + jj * (16 * PITCH));
                #pragma unroll
                for (int i = 0; i < 4; i++) {
                    mma_f16(acc[i][jj * 2 + 0], ah[i], bh2 + 0);
                    mma_f16(acc[i][jj * 2 + 1], ah[i], bh2 + 2);
                }
                #pragma unroll
                for (int i = 0; i < 4; i++) {
                    mma_f16(acc[i][jj * 2 + 0], ah[i], bl2 + 0);
                    mma_f16(acc[i][jj * 2 + 1], ah[i], bl2 + 2);
                }
            }
        }
    };

    issue(0);
    if (NC > 1) issue(1);

    #pragma unroll 1
    for (int c = 0; c < NC; c++) {
        if (c + 1 < NC) { CP_WAIT1(); } else { CP_WAIT0(); }
        __syncthreads();
        compute(c & 1);
        if (c + 2 < NC) {
            __syncthreads();
            issue(c + 2);
        }
    }

    // ---- epilogue ----
    #pragma unroll
    for (int i = 0; i < 4; i++) {
        #pragma unroll
        for (int half = 0; half < 2; half++) {
            int lr = wm * 64 + i * 16 + (lane >> 2) + half * 8;
            int gr = m0 + lr;
            if ((MODE == 2 || MODE == 3) && gr >= M) continue;
            float gate = 1.0f;
            int orow = gr;
            if (MODE == 3) {
                gate = g_glist[e * T_TOK + gr];
                orow = g_list[e * T_TOK + gr];
            }
            #pragma unroll
            for (int j = 0; j < 4; j++) {
                int col = wn * 32 + j * 8 + (lane & 3) * 2;
                float b0, b1;
                if (MODE == 4) {
                    int d = (n0 + col) >> 1;
                    b0 = bi[d];
                    b1 = bi[512 + d];
                } else {
                    b0 = (split == 0) ? bi[n0 + col]     : 0.0f;
                    b1 = (split == 0) ? bi[n0 + col + 1] : 0.0f;
                }
                float v0 = acc[i][j][half * 2 + 0] + b0;
                float v1 = acc[i][j][half * 2 + 1] + b1;
                if (MODE == 0 || MODE == 2) { v0 = gelu_tanh(v0); v1 = gelu_tanh(v1); }
                if (MODE == 3) { v0 *= gate; v1 *= gate; }
                if (MODE == 0) {
                    __half2 hv; hv.x = __float2half_rn(v0); hv.y = __float2half_rn(v1);
                    *(__half2*)&g_t116[(size_t)gr * DFF_DIM + n0 + col] = hv;
                }
                if (MODE == 1) {
                    float* outp = split ? g_sh2 : g_sh;
                    *(float2*)&outp[(size_t)gr * D_MODEL + n0 + col] = make_float2(v0, v1);
                }
                if (MODE == 2) {
                    __half2 hv; hv.x = __float2half_rn(v0); hv.y = __float2half_rn(v1);
                    *(__half2*)&g_h116[((size_t)e * T_TOK + gr) * H_HID + n0 + col] = hv;
                }
                if (MODE == 3) {
                    float* outp = split ? g_moe2b : g_moe2;
                    *(float2*)&outp[(size_t)orow * D_MODEL + n0 + col] = make_float2(v0, v1);
                }
                if (MODE == 4) {
                    int d = (n0 + col) >> 1;
                    float xl = __half2float(g_xln16[(size_t)gr * D_MODEL + d]);
                    g_xin16[(size_t)gr * D_MODEL + d] =
                        __float2half_rn(fmaf(xl, v0, xl + v1));
                }
            }
        }
    }
}

// L3: z=0 -> ffn1 (bx<16); z=1 -> film (bx<8). Both depend only on prep.
__global__ void __launch_bounds__(256, 2)
gemm_ffn1film(const float* __restrict__ fc1b, const float* __restrict__ film_b)
{
    extern __shared__ char sm[];
    if (blockIdx.z == 0) {
        gemm_body<0, DFF_DIM, D_MODEL, D_MODEL>(blockIdx.x, blockIdx.y, 0, 0, 0, fc1b, sm);
    } else {
        if (blockIdx.x >= 8) return;
        gemm_body<4, 1024, 64, 64>(blockIdx.x, blockIdx.y, 0, 0, 0, film_b, sm);
    }
}

// L4: z=0,1 -> ffn2 split z (bx<4); z=2..9 -> moe1 expert z-2 (bx<8)
__global__ void __launch_bounds__(256, 2)
gemm_moe1ffn2(const float* __restrict__ b1, const float* __restrict__ fc2b)
{
    extern __shared__ char sm[];
    if (blockIdx.z < 2) {
        if (blockIdx.x >= 4) return;
        int split = blockIdx.z;
        gemm_body<1, D_MODEL, DFF_DIM, DFF_DIM / 2>(blockIdx.x, blockIdx.y, 0,
                                                    split * (DFF_DIM / 2), split, fc2b, sm);
    } else {
        gemm_body<2, H_HID, D_MODEL, D_MODEL>(blockIdx.x, blockIdx.y, blockIdx.z - 2, 0, 0, b1, sm);
    }
}

// L5: moe2: z=0..15, e=z>>1, split=z&1 (bx<4)
__global__ void __launch_bounds__(256, 2)
gemm_moe2k(const float* __restrict__ b2)
{
    extern __shared__ char sm[];
    int e = blockIdx.z >> 1, split = blockIdx.z & 1;
    gemm_body<3, D_MODEL, H_HID, H_HID / 2>(blockIdx.x, blockIdx.y, e,
                                            split * (H_HID / 2), split, b2, sm);
}

// ---------------- final combine ----------------
__global__ void combine_kernel(const float* __restrict__ hid,
                               const float* __restrict__ alpha_p,
                               float* __restrict__ out)
{
    int idx = blockIdx.x * blockDim.x + threadIdx.x;
    float a = alpha_p[0];
    int t  = idx >> 7;
    int d4 = idx & 127;
    float4 h  = ((const float4*)hid)[idx];
    float4 s1 = ((const float4*)g_sh)[idx];
    float4 s2 = ((const float4*)g_sh2)[idx];
    float4 m0 = ((const float4*)g_moe2)[(size_t)(2 * t) * 128 + d4];
    float4 m1 = ((const float4*)g_moe2)[(size_t)(2 * t + 1) * 128 + d4];
    float4 n0 = ((const float4*)g_moe2b)[(size_t)(2 * t) * 128 + d4];
    float4 n1 = ((const float4*)g_moe2b)[(size_t)(2 * t + 1) * 128 + d4];
    float4 o;
    o.x = h.x + s1.x + s2.x + a * (m0.x + m1.x + n0.x + n1.x);
    o.y = h.y + s1.y + s2.y + a * (m0.y + m1.y + n0.y + n1.y);
    o.z = h.z + s1.z + s2.z + a * (m0.z + m1.z + n0.z + n1.z);
    o.w = h.w + s1.w + s2.w + a * (m0.w + m1.w + n0.w + n1.w);
    ((float4*)out)[idx] = o;
}

// ---------------- launch -------------------------------------------------------
extern "C" void kernel_launch(void* const* d_in, const int* in_sizes, int n_in,
                              void* d_out, int out_size)
{
    const float* hid    = (const float*)d_in[0];
    const float* raw    = (const float*)d_in[1];
    const float* ln_g   = (const float*)d_in[2];
    const float* ln_b   = (const float*)d_in[3];
    const float* pg     = (const float*)d_in[4];
    const float* pb     = (const float*)d_in[5];
    const float* feat_w = (const float*)d_in[6];
    const float* feat_b = (const float*)d_in[7];
    const float* film_w = (const float*)d_in[8];
    const float* film_b = (const float*)d_in[9];
    const float* rw     = (const float*)d_in[10];
    const float* rb     = (const float*)d_in[11];
    const float* w1     = (const float*)d_in[12];
    const float* b1     = (const float*)d_in[13];
    const float* w2     = (const float*)d_in[14];
    const float* b2     = (const float*)d_in[15];
    const float* fc1    = (const float*)d_in[16];
    const float* fc1b   = (const float*)d_in[17];
    const float* fc2    = (const float*)d_in[18];
    const float* fc2b   = (const float*)d_in[19];
    const float* alpha  = (const float*)d_in[20];
    float* out = (float*)d_out;

    cudaFuncSetAttribute(gemm_ffn1film, cudaFuncAttributeMaxDynamicSharedMemorySize, GSMEM_SZ);
    cudaFuncSetAttribute(gemm_moe1ffn2, cudaFuncAttributeMaxDynamicSharedMemorySize, GSMEM_SZ);
    cudaFuncSetAttribute(gemm_moe2k,    cudaFuncAttributeMaxDynamicSharedMemorySize, GSMEM_SZ);

    __half *fc1h_p, *fc1l_p, *fc2h_p, *fc2l_p, *w1h_p, *w1l_p, *w2h_p, *w2l_p, *fwh_p, *fwl_p;
    cudaGetSymbolAddress((void**)&fc1h_p, g_fc1h);
    cudaGetSymbolAddress((void**)&fc1l_p, g_fc1l);
    cudaGetSymbolAddress((void**)&fc2h_p, g_fc2h);
    cudaGetSymbolAddress((void**)&fc2l_p, g_fc2l);
    cudaGetSymbolAddress((void**)&w1h_p,  g_w1h);
    cudaGetSymbolAddress((void**)&w1l_p,  g_w1l);
    cudaGetSymbolAddress((void**)&w2h_p,  g_w2h);
    cudaGetSymbolAddress((void**)&w2l_p,  g_w2l);
    cudaGetSymbolAddress((void**)&fwh_p,  g_fwh);
    cudaGetSymbolAddress((void**)&fwl_p,  g_fwl);

    transpose_all<<<256 + 256 + 1024 + 1024 + 16, 256>>>(
        fc1, fc1h_p, fc1l_p, fc2, fc2h_p, fc2l_p,
        w1, w1h_p, w1l_p, w2, w2h_p, w2l_p, film_w, fwh_p, fwl_p);
    prep_kernel<<<T_TOK, 256>>>(hid, raw, ln_g, ln_b, pg, pb,
                                feat_w, feat_b, rw, rb);
    gemm_ffn1film<<<dim3(DFF_DIM / 128, T_TOK / 128, 2), 256, GSMEM_SZ>>>(fc1b, film_b);
    gemm_moe1ffn2<<<dim3(H_HID / 128, T_TOK / 128, 10), 256, GSMEM_SZ>>>(b1, fc2b);
    gemm_moe2k<<<dim3(D_MODEL / 128, T_TOK / 128, 16), 256, GSMEM_SZ>>>(b2);
    combine_kernel<<<(T_TOK * D_MODEL / 4) / 256, 256>>>(hid, alpha, out);
}

// round 17
// speedup vs baseline: 1.0220x; 1.0220x over previous
#include <cuda_runtime.h>
#include <cuda_fp16.h>
#include <math.h>
#include <stdint.h>

#define T_TOK 4096
#define D_MODEL 512
#define E_EXP 8
#define H_HID 1024
#define DFF_DIM 2048

// ---------------- scratch ------------------------------------------------------
__device__ __align__(16) __half g_xs16[T_TOK * D_MODEL];
__device__ __align__(16) __half g_xln16[T_TOK * D_MODEL];
__device__ __align__(16) __half g_xin16[T_TOK * D_MODEL];
__device__ __align__(16) __half g_feat16[T_TOK * 64];
__device__ __align__(16) __half g_t116[(size_t)T_TOK * DFF_DIM];
__device__ __align__(16) __half g_h116[(size_t)E_EXP * T_TOK * H_HID];
__device__ __align__(16) __half g_fc1h[(size_t)DFF_DIM * D_MODEL], g_fc1l[(size_t)DFF_DIM * D_MODEL];
__device__ __align__(16) __half g_fc2h[(size_t)D_MODEL * DFF_DIM], g_fc2l[(size_t)D_MODEL * DFF_DIM];
__device__ __align__(16) __half g_w1h[(size_t)E_EXP * H_HID * D_MODEL], g_w1l[(size_t)E_EXP * H_HID * D_MODEL];
__device__ __align__(16) __half g_w2h[(size_t)E_EXP * D_MODEL * H_HID], g_w2l[(size_t)E_EXP * D_MODEL * H_HID];
__device__ __align__(16) __half g_fwh[1024 * 64], g_fwl[1024 * 64];   // film_w^T, interleaved
__device__ __align__(16) float g_sh[T_TOK * D_MODEL];
__device__ __align__(16) float g_sh2[T_TOK * D_MODEL];
__device__ __align__(16) float g_moe2[T_TOK * 2 * D_MODEL];
__device__ __align__(16) float g_moe2b[T_TOK * 2 * D_MODEL];
__device__ int   g_cnt[E_EXP];
__device__ int   g_list[E_EXP * T_TOK];
__device__ float g_glist[E_EXP * T_TOK];

__device__ __forceinline__ float gelu_tanh(float x) {
    float x3 = x * x * x;
    return 0.5f * x * (1.0f + tanhf(0.7978845608028654f * (x + 0.044715f * x3)));
}

__device__ __forceinline__ uint32_t smem_u32(const void* p) {
    uint32_t a;
    asm("{ .reg .u64 t; cvta.to.shared.u64 t, %1; cvt.u32.u64 %0, t; }" : "=r"(a) : "l"(p));
    return a;
}

// ---------------- mma.sync / cp.async helpers ----------------------------------
__device__ __forceinline__ void ldmx4(uint32_t* r, uint32_t a) {
    asm volatile("ldmatrix.sync.aligned.m8n8.x4.shared.b16 {%0,%1,%2,%3}, [%4];"
                 : "=r"(r[0]), "=r"(r[1]), "=r"(r[2]), "=r"(r[3]) : "r"(a));
}
__device__ __forceinline__ void mma_f16(float* c, const uint32_t* a, const uint32_t* b) {
    asm volatile("mma.sync.aligned.m16n8k16.row.col.f32.f16.f16.f32 "
                 "{%0,%1,%2,%3}, {%4,%5,%6,%7}, {%8,%9}, {%0,%1,%2,%3};"
                 : "+f"(c[0]), "+f"(c[1]), "+f"(c[2]), "+f"(c[3])
                 : "r"(a[0]), "r"(a[1]), "r"(a[2]), "r"(a[3]), "r"(b[0]), "r"(b[1]));
}
__device__ __forceinline__ void cpa16(uint32_t dst, const void* src) {
    asm volatile("cp.async.cg.shared.global [%0], [%1], 16;" :: "r"(dst), "l"(src));
}
#define CP_COMMIT() asm volatile("cp.async.commit_group;" ::: "memory")
#define CP_WAIT1()  asm volatile("cp.async.wait_group 1;" ::: "memory")
#define CP_WAIT0()  asm volatile("cp.async.wait_group 0;" ::: "memory")

// ---------------- fused weight transposes (single launch) ----------------------
__device__ __forceinline__ void transpose_body(
    const float* __restrict__ in, __half* __restrict__ oh, __half* __restrict__ ol,
    int Kd, int Nd, int bx, int by, int bz, float* spool, bool il)
{
    in += (size_t)bz * Kd * Nd;
    oh += (size_t)bz * Kd * Nd;
    ol += (size_t)bz * Kd * Nd;
    int n0 = bx * 64, k0 = by * 64;
    int tid = threadIdx.x;
    int kr = tid >> 4, n4 = (tid & 15) * 4;
    #pragma unroll
    for (int it = 0; it < 4; it++) {
        int k = kr + it * 16;
        float4 v = *(const float4*)&in[(size_t)(k0 + k) * Nd + n0 + n4];
        spool[k * 65 + n4 + 0] = v.x; spool[k * 65 + n4 + 1] = v.y;
        spool[k * 65 + n4 + 2] = v.z; spool[k * 65 + n4 + 3] = v.w;
    }
    __syncthreads();
    int n = tid >> 2, kc = (tid & 3) * 16;
    __half hbuf[16], lbuf[16];
    #pragma unroll
    for (int i = 0; i < 16; i++) {
        float v = spool[(kc + i) * 65 + n];
        __half h = __float2half_rn(v);
        hbuf[i] = h;
        lbuf[i] = __float2half_rn(v - __half2float(h));
    }
    int gn = n0 + n;
    int orow = il ? ((gn < 512) ? 2 * gn : 2 * (gn - 512) + 1) : gn;
    size_t base = (size_t)orow * Kd + k0 + kc;
    *(uint4*)&oh[base]     = *(uint4*)&hbuf[0];
    *(uint4*)&oh[base + 8] = *(uint4*)&hbuf[8];
    *(uint4*)&ol[base]     = *(uint4*)&lbuf[0];
    *(uint4*)&ol[base + 8] = *(uint4*)&lbuf[8];
}

// blocks: fc1 256 | fc2 256 | w1 1024 | w2 1024 | filmw 16  = 2576
__global__ void __launch_bounds__(256)
transpose_all(const float* __restrict__ fc1, __half* fc1h, __half* fc1l,
              const float* __restrict__ fc2, __half* fc2h, __half* fc2l,
              const float* __restrict__ w1,  __half* w1h,  __half* w1l,
              const float* __restrict__ w2,  __half* w2h,  __half* w2l,
              const float* __restrict__ fw,  __half* fwh,  __half* fwl)
{
    __shared__ __align__(16) float spool[64 * 65];
    if (blockIdx.x == 0 && threadIdx.x < E_EXP) g_cnt[threadIdx.x] = 0;
    int idx = blockIdx.x;
    if (idx < 256) {
        transpose_body(fc1, fc1h, fc1l, D_MODEL, DFF_DIM, idx & 31, idx >> 5, 0, spool, false);
        return;
    }
    idx -= 256;
    if (idx < 256) {
        transpose_body(fc2, fc2h, fc2l, DFF_DIM, D_MODEL, idx & 7, idx >> 3, 0, spool, false);
        return;
    }
    idx -= 256;
    if (idx < 1024) {
        transpose_body(w1, w1h, w1l, D_MODEL, H_HID, idx & 15, (idx >> 4) & 7, idx >> 7, spool, false);
        return;
    }
    idx -= 1024;
    if (idx < 1024) {
        transpose_body(w2, w2h, w2l, H_HID, D_MODEL, idx & 7, (idx >> 3) & 15, idx >> 7, spool, false);
        return;
    }
    idx -= 1024;  // film_w [64,1024] -> [1024,64] interleaved
    transpose_body(fw, fwh, fwl, 64, 1024, idx, 0, 0, spool, true);
}

// ---------------- per-token prep: LN x2, feat, router ---------------------------
__global__ void prep_kernel(
    const float* __restrict__ hid, const float* __restrict__ raw,
    const float* __restrict__ ln_g, const float* __restrict__ ln_b,
    const float* __restrict__ pg,   const float* __restrict__ pb,
    const float* __restrict__ feat_w, const float* __restrict__ feat_b,
    const float* __restrict__ rw, const float* __restrict__ rb)
{
    int t = blockIdx.x;
    int tid = threadIdx.x;
    int wid = tid >> 5, lane = tid & 31;

    __shared__ float red[8];
    __shared__ float red2[8];
    __shared__ float s_x[D_MODEL];
    __shared__ float s_logits[E_EXP];

    float h0 = hid[t * D_MODEL + tid];
    float h1 = hid[t * D_MODEL + 256 + tid];

    float p = h0 + h1;
    #pragma unroll
    for (int off = 16; off; off >>= 1) p += __shfl_down_sync(0xffffffff, p, off);
    if (lane == 0) red[wid] = p;
    __syncthreads();
    float mean = (red[0] + red[1] + red[2] + red[3] +
                  red[4] + red[5] + red[6] + red[7]) * (1.0f / 512.0f);

    float d0 = h0 - mean, d1 = h1 - mean;
    float q = d0 * d0 + d1 * d1;
    #pragma unroll
    for (int off = 16; off; off >>= 1) q += __shfl_down_sync(0xffffffff, q, off);
    if (lane == 0) red2[wid] = q;
    __syncthreads();
    float inv = rsqrtf((red2[0] + red2[1] + red2[2] + red2[3] +
                        red2[4] + red2[5] + red2[6] + red2[7]) * (1.0f / 512.0f) + 1e-5f);

    float x0 = d0 * inv, x1 = d1 * inv;
    float xl0 = x0 * ln_g[tid]       + ln_b[tid];
    float xl1 = x1 * ln_g[tid + 256] + ln_b[tid + 256];
    s_x[tid]       = xl0;
    s_x[tid + 256] = xl1;
    g_xln16[(size_t)t * D_MODEL + tid]       = __float2half_rn(xl0);
    g_xln16[(size_t)t * D_MODEL + tid + 256] = __float2half_rn(xl1);
    g_xs16[(size_t)t * D_MODEL + tid]       = __float2half_rn(x0 * pg[tid]       + pb[tid]);
    g_xs16[(size_t)t * D_MODEL + tid + 256] = __float2half_rn(x1 * pg[tid + 256] + pb[tid + 256]);

    if (tid < 64) {
        float acc = feat_b[tid];
        #pragma unroll
        for (int i = 0; i < 16; i++) acc += raw[t * 16 + i] * feat_w[i * 64 + tid];
        g_feat16[t * 64 + tid] = __float2half_rn(acc);
    }
    __syncthreads();

    {
        int w = tid >> 5;
        float acc = 0.0f;
        #pragma unroll
        for (int d = 0; d < 512; d += 32) acc += s_x[d + lane] * rw[(d + lane) * E_EXP + w];
        #pragma unroll
        for (int off = 16; off; off >>= 1) acc += __shfl_down_sync(0xffffffff, acc, off);
        if (lane == 0) s_logits[w] = acc + rb[w];
    }
    __syncthreads();

    if (tid == 0) {
        int i0 = 0; float v0 = s_logits[0];
        #pragma unroll
        for (int e = 1; e < E_EXP; e++) { float v = s_logits[e]; if (v > v0) { v0 = v; i0 = e; } }
        int i1 = -1; float v1 = -1e30f;
        #pragma unroll
        for (int e = 0; e < E_EXP; e++) {
            if (e == i0) continue;
            float v = s_logits[e]; if (v > v1) { v1 = v; i1 = e; }
        }
        float b  = expf(v1 - v0);
        float g0 = 1.0f / (1.0f + b);
        float g1 = b * g0;
        int p0 = atomicAdd(&g_cnt[i0], 1);
        g_list[i0 * T_TOK + p0] = t * 2 + 0;  g_glist[i0 * T_TOK + p0] = g0;
        int p1 = atomicAdd(&g_cnt[i1], 1);
        g_list[i1 * T_TOK + p1] = t * 2 + 1;  g_glist[i1 * T_TOK + p1] = g1;
    }
}

// ---------------- GEMM: CTA 128x128, 8 warps 64x32, fp16 2-term ----------------
// K-chunk 64 (144B pitch), 2 stages, 2 CTA/SM. Hoisted cp.async addressing.
#define PITCH 144
#define A_SZ 18432
#define STAGE_SZ 55296
#define GSMEM_SZ (1024 + 2 * STAGE_SZ)   // 111616 -> 2 CTAs/SM

template<int MODE, int N, int KT, int KL>
__device__ __forceinline__ void gemm_body(int bx, int by, int e, int koff, int split,
                                          const float* __restrict__ bi0, char* sm)
{
    constexpr int NC = KL / 64;
    int M = T_TOK;
    if (MODE == 2 || MODE == 3) M = g_cnt[e];
    const int m0 = by * 128;
    if (m0 >= M) return;
    const int n0 = bx * 128;

    const __half *A16, *Bh, *Bl;
    if (MODE == 0) { A16 = g_xs16;  Bh = g_fc1h; Bl = g_fc1l; }
    if (MODE == 1) { A16 = g_t116;  Bh = g_fc2h; Bl = g_fc2l; }
    if (MODE == 2) { A16 = g_xin16;
                     Bh = g_w1h + (size_t)e * N * KT; Bl = g_w1l + (size_t)e * N * KT; }
    if (MODE == 3) { A16 = g_h116 + (size_t)e * T_TOK * KT;
                     Bh = g_w2h + (size_t)e * N * KT; Bl = g_w2l + (size_t)e * N * KT; }
    if (MODE == 4) { A16 = g_feat16; Bh = g_fwh; Bl = g_fwl; }
    const float* bi = bi0 + ((MODE == 2 || MODE == 3) ? e * N : 0);

    int* s_tok = (int*)sm;
    const int tid = threadIdx.x;
    const int wid = tid >> 5, lane = tid & 31;
    const int wm = wid & 1, wn = wid >> 1;

    if (MODE == 2 && tid < 128) {
        int r = m0 + tid;
        s_tok[tid] = (r < M) ? (g_list[e * T_TOK + r] >> 1) : 0;
    }
    __syncthreads();

    const uint32_t smb = smem_u32(sm);

    // hoisted cp.async addressing
    const int row0 = tid >> 3;
    const int cel  = (tid & 7) * 8;
    const __half* pA[4];
    #pragma unroll
    for (int u = 0; u < 4; u++) {
        int r = (MODE == 2) ? s_tok[row0 + 32 * u] : (m0 + row0 + 32 * u);
        pA[u] = A16 + (size_t)r * KT + koff + cel;
    }
    const __half* pBh = Bh + (size_t)(n0 + row0) * KT + koff + cel;
    const __half* pBl = Bl + (size_t)(n0 + row0) * KT + koff + cel;
    const uint32_t dbase = row0 * PITCH + (tid & 7) * 16;

    float acc[4][4][4];
    #pragma unroll
    for (int i = 0; i < 4; i++)
        #pragma unroll
        for (int j = 0; j < 4; j++)
            #pragma unroll
            for (int q = 0; q < 4; q++) acc[i][j][q] = 0.0f;

    auto issue = [&](int c) {
        uint32_t st = smb + 1024 + (c & 1) * STAGE_SZ + dbase;
        const int kb = c * 64;
        #pragma unroll
        for (int u = 0; u < 4; u++)
            cpa16(st + u * (32 * PITCH), pA[u] + kb);
        #pragma unroll
        for (int u = 0; u < 4; u++)
            cpa16(st + A_SZ + u * (32 * PITCH), pBh + (size_t)u * 32 * KT + kb);
        #pragma unroll
        for (int u = 0; u < 4; u++)
            cpa16(st + 2 * A_SZ + u * (32 * PITCH), pBl + (size_t)u * 32 * KT + kb);
        CP_COMMIT();
    };

    auto compute = [&](int s) {
        const uint32_t base = smb + 1024 + s * STAGE_SZ;
        #pragma unroll
        for (int ks = 0; ks < 4; ks++) {
            uint32_t ah[4][4];
            uint32_t a_ad = base + ((uint32_t)(wm * 64 + (lane & 15)) * PITCH
                                    + (uint32_t)(ks * 16 + (lane >> 4) * 8) * 2u);
            #pragma unroll
            for (int i = 0; i < 4; i++) ldmx4(ah[i], a_ad + i * (16 * PITCH));
            uint32_t b_ad = base + A_SZ
                + ((uint32_t)(wn * 32 + (lane >> 4) * 8 + (lane & 7)) * PITCH
                   + (uint32_t)(ks * 16 + ((lane >> 3) & 1) * 8) * 2u);
            #pragma unroll
            for (int jj = 0; jj < 2; jj++) {
                uint32_t bh2[4], bl2[4];
                ldmx4(bh2, b_ad + jj * (16 * PITCH));
                ldmx4(bl2, b_ad + A_SZ + jj * (16 * PITCH));
                #pragma unroll
                for (int i = 0; i < 4; i++) {
                    mma_f16(acc[i][jj * 2 + 0], ah[i], bh2 + 0);
                    mma_f16(acc[i][jj * 2 + 1], ah[i], bh2 + 2);
                }
                #pragma unroll
                for (int i = 0; i < 4; i++) {
                    mma_f16(acc[i][jj * 2 + 0], ah[i], bl2 + 0);
                    mma_f16(acc[i][jj * 2 + 1], ah[i], bl2 + 2);
                }
            }
        }
    };

    issue(0);
    if (NC > 1) issue(1);

    #pragma unroll 1
    for (int c = 0; c < NC; c++) {
        if (c + 1 < NC) { CP_WAIT1(); } else { CP_WAIT0(); }
        __syncthreads();
        compute(c & 1);
        if (c + 2 < NC) {
            __syncthreads();
            issue(c + 2);
        }
    }

    // ---- epilogue ----
    #pragma unroll
    for (int i = 0; i < 4; i++) {
        #pragma unroll
        for (int half = 0; half < 2; half++) {
            int lr = wm * 64 + i * 16 + (lane >> 2) + half * 8;
            int gr = m0 + lr;
            if ((MODE == 2 || MODE == 3) && gr >= M) continue;
            float gate = 1.0f;
            int orow = gr;
            if (MODE == 3) {
                gate = g_glist[e * T_TOK + gr];
                orow = g_list[e * T_TOK + gr];
            }
            #pragma unroll
            for (int j = 0; j < 4; j++) {
                int col = wn * 32 + j * 8 + (lane & 3) * 2;
                float b0, b1;
                if (MODE == 4) {
                    int d = (n0 + col) >> 1;
                    b0 = bi[d];
                    b1 = bi[512 + d];
                } else {
                    b0 = (split == 0) ? bi[n0 + col]     : 0.0f;
                    b1 = (split == 0) ? bi[n0 + col + 1] : 0.0f;
                }
                float v0 = acc[i][j][half * 2 + 0] + b0;
                float v1 = acc[i][j][half * 2 + 1] + b1;
                if (MODE == 0 || MODE == 2) { v0 = gelu_tanh(v0); v1 = gelu_tanh(v1); }
                if (MODE == 3) { v0 *= gate; v1 *= gate; }
                if (MODE == 0) {
                    __half2 hv; hv.x = __float2half_rn(v0); hv.y = __float2half_rn(v1);
                    *(__half2*)&g_t116[(size_t)gr * DFF_DIM + n0 + col] = hv;
                }
                if (MODE == 1) {
                    float* outp = split ? g_sh2 : g_sh;
                    *(float2*)&outp[(size_t)gr * D_MODEL + n0 + col] = make_float2(v0, v1);
                }
                if (MODE == 2) {
                    __half2 hv; hv.x = __float2half_rn(v0); hv.y = __float2half_rn(v1);
                    *(__half2*)&g_h116[((size_t)e * T_TOK + gr) * H_HID + n0 + col] = hv;
                }
                if (MODE == 3) {
                    float* outp = split ? g_moe2b : g_moe2;
                    *(float2*)&outp[(size_t)orow * D_MODEL + n0 + col] = make_float2(v0, v1);
                }
                if (MODE == 4) {
                    int d = (n0 + col) >> 1;
                    float xl = __half2float(g_xln16[(size_t)gr * D_MODEL + d]);
                    g_xin16[(size_t)gr * D_MODEL + d] =
                        __float2half_rn(fmaf(xl, v0, xl + v1));
                }
            }
        }
    }
}

// film GEMM + FiLM apply: grid (8, 32)
__global__ void __launch_bounds__(256, 2)
gemm_film(const float* __restrict__ film_b)
{
    extern __shared__ char sm[];
    gemm_body<4, 1024, 64, 64>(blockIdx.x, blockIdx.y, 0, 0, 0, film_b, sm);
}

// stage A: z=0 -> ffn1 (bx<16), z=1..8 -> moe1 expert z-1 (bx<8)
__global__ void __launch_bounds__(256, 2)
gemm_stageA(const float* __restrict__ fc1b, const float* __restrict__ b1)
{
    extern __shared__ char sm[];
    if (blockIdx.z == 0) {
        gemm_body<0, DFF_DIM, D_MODEL, D_MODEL>(blockIdx.x, blockIdx.y, 0, 0, 0, fc1b, sm);
    } else {
        if (blockIdx.x >= H_HID / 128) return;
        gemm_body<2, H_HID, D_MODEL, D_MODEL>(blockIdx.x, blockIdx.y, blockIdx.z - 1, 0, 0, b1, sm);
    }
}

// stage B (split-K 2): z=0,1 -> ffn2 split z; z=2..17 -> moe2 e=(z-2)/2, split=(z-2)&1
__global__ void __launch_bounds__(256, 2)
gemm_stageB(const float* __restrict__ fc2b, const float* __restrict__ b2)
{
    extern __shared__ char sm[];
    if (blockIdx.z < 2) {
        int split = blockIdx.z;
        gemm_body<1, D_MODEL, DFF_DIM, DFF_DIM / 2>(blockIdx.x, blockIdx.y, 0,
                                                    split * (DFF_DIM / 2), split, fc2b, sm);
    } else {
        int zz = blockIdx.z - 2;
        int e = zz >> 1, split = zz & 1;
        gemm_body<3, D_MODEL, H_HID, H_HID / 2>(blockIdx.x, blockIdx.y, e,
                                                split * (H_HID / 2), split, b2, sm);
    }
}

// ---------------- final combine ----------------
__global__ void combine_kernel(const float* __restrict__ hid,
                               const float* __restrict__ alpha_p,
                               float* __restrict__ out)
{
    int idx = blockIdx.x * blockDim.x + threadIdx.x;
    float a = alpha_p[0];
    int t  = idx >> 7;
    int d4 = idx & 127;
    float4 h  = ((const float4*)hid)[idx];
    float4 s1 = ((const float4*)g_sh)[idx];
    float4 s2 = ((const float4*)g_sh2)[idx];
    float4 m0 = ((const float4*)g_moe2)[(size_t)(2 * t) * 128 + d4];
    float4 m1 = ((const float4*)g_moe2)[(size_t)(2 * t + 1) * 128 + d4];
    float4 n0 = ((const float4*)g_moe2b)[(size_t)(2 * t) * 128 + d4];
    float4 n1 = ((const float4*)g_moe2b)[(size_t)(2 * t + 1) * 128 + d4];
    float4 o;
    o.x = h.x + s1.x + s2.x + a * (m0.x + m1.x + n0.x + n1.x);
    o.y = h.y + s1.y + s2.y + a * (m0.y + m1.y + n0.y + n1.y);
    o.z = h.z + s1.z + s2.z + a * (m0.z + m1.z + n0.z + n1.z);
    o.w = h.w + s1.w + s2.w + a * (m0.w + m1.w + n0.w + n1.w);
    ((float4*)out)[idx] = o;
}

// ---------------- launch -------------------------------------------------------
extern "C" void kernel_launch(void* const* d_in, const int* in_sizes, int n_in,
                              void* d_out, int out_size)
{
    const float* hid    = (const float*)d_in[0];
    const float* raw    = (const float*)d_in[1];
    const float* ln_g   = (const float*)d_in[2];
    const float* ln_b   = (const float*)d_in[3];
    const float* pg     = (const float*)d_in[4];
    const float* pb     = (const float*)d_in[5];
    const float* feat_w = (const float*)d_in[6];
    const float* feat_b = (const float*)d_in[7];
    const float* film_w = (const float*)d_in[8];
    const float* film_b = (const float*)d_in[9];
    const float* rw     = (const float*)d_in[10];
    const float* rb     = (const float*)d_in[11];
    const float* w1     = (const float*)d_in[12];
    const float* b1     = (const float*)d_in[13];
    const float* w2     = (const float*)d_in[14];
    const float* b2     = (const float*)d_in[15];
    const float* fc1    = (const float*)d_in[16];
    const float* fc1b   = (const float*)d_in[17];
    const float* fc2    = (const float*)d_in[18];
    const float* fc2b   = (const float*)d_in[19];
    const float* alpha  = (const float*)d_in[20];
    float* out = (float*)d_out;

    cudaFuncSetAttribute(gemm_film,   cudaFuncAttributeMaxDynamicSharedMemorySize, GSMEM_SZ);
    cudaFuncSetAttribute(gemm_stageA, cudaFuncAttributeMaxDynamicSharedMemorySize, GSMEM_SZ);
    cudaFuncSetAttribute(gemm_stageB, cudaFuncAttributeMaxDynamicSharedMemorySize, GSMEM_SZ);

    __half *fc1h_p, *fc1l_p, *fc2h_p, *fc2l_p, *w1h_p, *w1l_p, *w2h_p, *w2l_p, *fwh_p, *fwl_p;
    cudaGetSymbolAddress((void**)&fc1h_p, g_fc1h);
    cudaGetSymbolAddress((void**)&fc1l_p, g_fc1l);
    cudaGetSymbolAddress((void**)&fc2h_p, g_fc2h);
    cudaGetSymbolAddress((void**)&fc2l_p, g_fc2l);
    cudaGetSymbolAddress((void**)&w1h_p,  g_w1h);
    cudaGetSymbolAddress((void**)&w1l_p,  g_w1l);
    cudaGetSymbolAddress((void**)&w2h_p,  g_w2h);
    cudaGetSymbolAddress((void**)&w2l_p,  g_w2l);
    cudaGetSymbolAddress((void**)&fwh_p,  g_fwh);
    cudaGetSymbolAddress((void**)&fwl_p,  g_fwl);

    transpose_all<<<256 + 256 + 1024 + 1024 + 16, 256>>>(
        fc1, fc1h_p, fc1l_p, fc2, fc2h_p, fc2l_p,
        w1, w1h_p, w1l_p, w2, w2h_p, w2l_p, film_w, fwh_p, fwl_p);
    prep_kernel<<<T_TOK, 256>>>(hid, raw, ln_g, ln_b, pg, pb,
                                feat_w, feat_b, rw, rb);
    gemm_film<<<dim3(1024 / 128, T_TOK / 128), 256, GSMEM_SZ>>>(film_b);
    gemm_stageA<<<dim3(DFF_DIM / 128, T_TOK / 128, 1 + E_EXP), 256, GSMEM_SZ>>>(fc1b, b1);
    gemm_stageB<<<dim3(D_MODEL / 128, T_TOK / 128, 2 + 2 * E_EXP), 256, GSMEM_SZ>>>(fc2b, b2);
    combine_kernel<<<(T_TOK * D_MODEL / 4) / 256, 256>>>(hid, alpha, out);
}